// round 2
// baseline (speedup 1.0000x reference)
#include <cuda_runtime.h>
#include <math.h>

#define S_LEN  4096
#define DMODEL 1024
#define DHEAD  64
#define NBATCH 2
#define NROWS  (NBATCH * S_LEN)   // 8192

// Scratch for projected q, k, v: [NROWS][DHEAD] each (2 MB apiece, 6 MB total -> lives in L2)
__device__ float g_q[NROWS * DHEAD];
__device__ float g_k[NROWS * DHEAD];
__device__ float g_v[NROWS * DHEAD];

// ---------------------------------------------------------------------------
// Projection SGEMM: C[row][k] = sum_m A[row][m] * W[k][m] + b[k]
// A: [8192, 1024], W: [64, 1024] (both m-contiguous -> coalesced loads)
// 64-row tile per block, full 64 output cols, K-chunks of 16.
// 256 threads as 16x16 grid, 4x4 register microtile each.
// ---------------------------------------------------------------------------
__global__ __launch_bounds__(256) void proj_kernel(
    const float* __restrict__ Qin, const float* __restrict__ Kin,
    const float* __restrict__ Vin,
    const float* __restrict__ Wq, const float* __restrict__ bq,
    const float* __restrict__ Wk, const float* __restrict__ bk,
    const float* __restrict__ Wv, const float* __restrict__ bv)
{
    const float* A; const float* W; const float* bias; float* C;
    int which = blockIdx.y;
    if (which == 0)      { A = Qin; W = Wq; bias = bq; C = g_q; }
    else if (which == 1) { A = Kin; W = Wk; bias = bk; C = g_k; }
    else                 { A = Vin; W = Wv; bias = bv; C = g_v; }

    __shared__ float As[16][64];   // As[m][row]
    __shared__ float Ws[16][64];   // Ws[m][col]

    const int tid = threadIdx.x;
    const int tx  = tid & 15, ty = tid >> 4;
    const int lr  = tid >> 2, lq = tid & 3;   // 16-deep chunk: 16x64 = 256 threads * 4
    const int row0 = blockIdx.x * 64;

    float acc[4][4] = {};

    const float* Arow = A + (size_t)(row0 + lr) * DMODEL + 4 * lq;
    const float* Wrow = W + (size_t)lr * DMODEL + 4 * lq;

    for (int k0 = 0; k0 < DMODEL; k0 += 16) {
        float4 av = *(const float4*)(Arow + k0);
        float4 wv = *(const float4*)(Wrow + k0);
        As[4*lq+0][lr] = av.x; As[4*lq+1][lr] = av.y;
        As[4*lq+2][lr] = av.z; As[4*lq+3][lr] = av.w;
        Ws[4*lq+0][lr] = wv.x; Ws[4*lq+1][lr] = wv.y;
        Ws[4*lq+2][lr] = wv.z; Ws[4*lq+3][lr] = wv.w;
        __syncthreads();

        #pragma unroll
        for (int m = 0; m < 16; m++) {
            float4 a4 = *(const float4*)&As[m][4*ty];
            float4 w4 = *(const float4*)&Ws[m][4*tx];
            float af[4] = {a4.x, a4.y, a4.z, a4.w};
            float wf[4] = {w4.x, w4.y, w4.z, w4.w};
            #pragma unroll
            for (int i = 0; i < 4; i++)
                #pragma unroll
                for (int j = 0; j < 4; j++)
                    acc[i][j] = fmaf(af[i], wf[j], acc[i][j]);
        }
        __syncthreads();
    }

    float4 b4 = *(const float4*)&bias[4*tx];
    float bf[4] = {b4.x, b4.y, b4.z, b4.w};
    #pragma unroll
    for (int i = 0; i < 4; i++) {
        float4 o4 = make_float4(acc[i][0] + bf[0], acc[i][1] + bf[1],
                                acc[i][2] + bf[2], acc[i][3] + bf[3]);
        *(float4*)&C[(size_t)(row0 + 4*ty + i) * DHEAD + 4*tx] = o4;
    }
}

// ---------------------------------------------------------------------------
// Flash attention: 64 queries x full 4096 keys per block.
// Tiles are 64x64 = 4096 floats: each of 256 threads loads FOUR float4s
// (row = (tid>>4) + 16*r, col4 = (tid&15)*4).   <-- round-1 bug fix
// ---------------------------------------------------------------------------
__global__ __launch_bounds__(256) void attn_kernel(const int* __restrict__ mask,
                                                   float* __restrict__ out)
{
    __shared__ float qt[64][64];   // qt[d][row]
    __shared__ float kt[64][64];   // kt[d][key]  ... then pt[key][row]
    __shared__ float vs[64][64];   // vs[key][vcol]

    const int tid = threadIdx.x;
    const int tx  = tid & 15, ty = tid >> 4;
    const int cr  = tid >> 4;          // 0..15 base row for tile loads
    const int c4  = (tid & 15) * 4;    // 0..60 col group for tile loads
    const int b   = blockIdx.y;
    const int q0  = blockIdx.x * 64;

    // load q tile transposed & pre-scaled by 1/sqrt(64); full 64x64 tile
    #pragma unroll
    for (int r = 0; r < 4; r++) {
        int row = cr + 16 * r;
        float4 qv = *(const float4*)(g_q + (size_t)(b * S_LEN + q0 + row) * DHEAD + c4);
        qt[c4+0][row] = qv.x * 0.125f;
        qt[c4+1][row] = qv.y * 0.125f;
        qt[c4+2][row] = qv.z * 0.125f;
        qt[c4+3][row] = qv.w * 0.125f;
    }

    float m_run[4], l_run[4], o[4][4] = {};
    #pragma unroll
    for (int i = 0; i < 4; i++) { m_run[i] = -INFINITY; l_run[i] = 0.f; }

    const int* mbase = mask + (size_t)(b * S_LEN + q0 + 4*ty) * S_LEN + 4*tx;

    for (int kk0 = 0; kk0 < S_LEN; kk0 += 64) {
        // issue all global loads for this tile before the sync
        float4 kv[4], vv[4];
        #pragma unroll
        for (int r = 0; r < 4; r++) {
            int row = cr + 16 * r;
            kv[r] = *(const float4*)(g_k + (size_t)(b * S_LEN + kk0 + row) * DHEAD + c4);
            vv[r] = *(const float4*)(g_v + (size_t)(b * S_LEN + kk0 + row) * DHEAD + c4);
        }
        __syncthreads();   // previous iter's pt/vs readers done
        #pragma unroll
        for (int r = 0; r < 4; r++) {
            int row = cr + 16 * r;
            kt[c4+0][row] = kv[r].x; kt[c4+1][row] = kv[r].y;
            kt[c4+2][row] = kv[r].z; kt[c4+3][row] = kv[r].w;
            *(float4*)&vs[row][c4] = vv[r];
        }
        __syncthreads();

        // ----- S tile: s[r][c] = sum_d q[r][d] k[c][d] (q pre-scaled) -----
        float s[4][4] = {};
        #pragma unroll
        for (int d = 0; d < 64; d++) {
            float4 a4 = *(const float4*)&qt[d][4*ty];
            float4 k4 = *(const float4*)&kt[d][4*tx];
            float af[4] = {a4.x, a4.y, a4.z, a4.w};
            float kf[4] = {k4.x, k4.y, k4.z, k4.w};
            #pragma unroll
            for (int i = 0; i < 4; i++)
                #pragma unroll
                for (int j = 0; j < 4; j++)
                    s[i][j] = fmaf(af[i], kf[j], s[i][j]);
        }

        // ----- mask + online softmax -----
        float p[4][4];
        #pragma unroll
        for (int i = 0; i < 4; i++) {
            int4 mm = *(const int4*)(mbase + (size_t)i * S_LEN + kk0);
            float lg0 = mm.x ? s[i][0] : -1e9f;
            float lg1 = mm.y ? s[i][1] : -1e9f;
            float lg2 = mm.z ? s[i][2] : -1e9f;
            float lg3 = mm.w ? s[i][3] : -1e9f;
            float mx = fmaxf(fmaxf(lg0, lg1), fmaxf(lg2, lg3));
            #pragma unroll
            for (int off = 1; off < 16; off <<= 1)
                mx = fmaxf(mx, __shfl_xor_sync(0xffffffffu, mx, off));
            float nm = fmaxf(m_run[i], mx);
            float ef = __expf(m_run[i] - nm);   // exp(-inf)=0 on first tile
            m_run[i] = nm;
            l_run[i] *= ef;
            o[i][0] *= ef; o[i][1] *= ef; o[i][2] *= ef; o[i][3] *= ef;
            p[i][0] = __expf(lg0 - nm);
            p[i][1] = __expf(lg1 - nm);
            p[i][2] = __expf(lg2 - nm);
            p[i][3] = __expf(lg3 - nm);
            l_run[i] += p[i][0] + p[i][1] + p[i][2] + p[i][3];
        }

        __syncthreads();   // all S-tile reads of kt complete
        // store P transposed into kt: pt[key][row]
        #pragma unroll
        for (int i = 0; i < 4; i++)
            #pragma unroll
            for (int j = 0; j < 4; j++)
                kt[4*tx + j][4*ty + i] = p[i][j];
        __syncthreads();

        // ----- O += P * V : o[r][c] += pt[k][r] * vs[k][c] -----
        #pragma unroll
        for (int kk = 0; kk < 64; kk++) {
            float4 a4 = *(const float4*)&kt[kk][4*ty];
            float4 v4 = *(const float4*)&vs[kk][4*tx];
            float pf[4] = {a4.x, a4.y, a4.z, a4.w};
            float vf[4] = {v4.x, v4.y, v4.z, v4.w};
            #pragma unroll
            for (int i = 0; i < 4; i++)
                #pragma unroll
                for (int j = 0; j < 4; j++)
                    o[i][j] = fmaf(pf[i], vf[j], o[i][j]);
        }
    }

    // reduce row-sums across the 16-lane column group
    #pragma unroll
    for (int i = 0; i < 4; i++) {
        float l = l_run[i];
        #pragma unroll
        for (int off = 1; off < 16; off <<= 1)
            l += __shfl_xor_sync(0xffffffffu, l, off);
        l_run[i] = l;
    }

    #pragma unroll
    for (int i = 0; i < 4; i++) {
        float inv = 1.f / l_run[i];
        float4 o4 = make_float4(o[i][0] * inv, o[i][1] * inv,
                                o[i][2] * inv, o[i][3] * inv);
        *(float4*)&out[(size_t)(b * S_LEN + q0 + 4*ty + i) * DHEAD + 4*tx] = o4;
    }
}

extern "C" void kernel_launch(void* const* d_in, const int* in_sizes, int n_in,
                              void* d_out, int out_size)
{
    const float* Q    = (const float*)d_in[0];
    const float* K    = (const float*)d_in[1];
    const float* V    = (const float*)d_in[2];
    const int*   mask = (const int*)  d_in[3];
    const float* Wq   = (const float*)d_in[4];
    const float* bq   = (const float*)d_in[5];
    const float* Wk   = (const float*)d_in[6];
    const float* bk   = (const float*)d_in[7];
    const float* Wv   = (const float*)d_in[8];
    const float* bv   = (const float*)d_in[9];
    float* out = (float*)d_out;

    dim3 pgrid(NROWS / 64, 3);
    proj_kernel<<<pgrid, 256>>>(Q, K, V, Wq, bq, Wk, bk, Wv, bv);

    dim3 agrid(S_LEN / 64, NBATCH);
    attn_kernel<<<agrid, 256>>>(mask, out);
}